// round 17
// baseline (speedup 1.0000x reference)
#include <cuda_runtime.h>
#include <cuda_fp16.h>
#include <math.h>

#define NB    256
#define TP    32
#define TFUT  256
#define HH    100
#define NF    275
#define HGG   75
#define HOO   75
#define NTHR  576
#define NCTA  128

typedef unsigned long long ull;

// ---- weights in global scratch (layouts identical to R13) ----
// W1P fp32 paired: W1P[(kp*275+n)*2+r], k=2kp+r, kp 0..51 (k>=101 zero)
__device__ __align__(16) float g_W1P[28600];
// W3 fp16 paired: g_W3H[kp*100+n] = half2(W3[n][2kp], W3[n][2kp+1]), kp 0..139 (k>=275 zero)
__device__ __align__(16) unsigned int g_W3H[14000];
// W2 fp16: g_W2H[k*138+j] = half2(W2[2j][k], W2[2j+1][k]); k 0..275 (row 275 zero)
__device__ __align__(16) __half2 g_W2H[276 * 138];
__device__ __align__(16) float g_WhhT[100 * 300];
__device__ __align__(16) float g_oW1T[100 * 75];
__device__ __align__(16) float g_oW2T[75 * 75];
__device__ float g_hB[NB * HH];
__device__ float g_gx[NB * 2];
__device__ float g_z0[NB * HH];

// ---- shared layout (float offsets), total 45976 floats = 183,904 B ----
#define OFF_W1P  0        // 28600 floats
#define OFF_W3H  28600    // 14000 uints
#define OFF_IN   42600    // float2[104] (101..103 zero)
#define OFF_HID  42808    // float2[276] (275 zero)
#define OFF_A2   43360    // float2[280] (276..279 zero)
#define OFF_Y    43920    // float2[100]
#define OFF_KS   44120    // float2[100]
#define OFF_PART 44320    // 1656 floats scratch
#define SMEM_BYTES (45976 * 4)

__device__ __forceinline__ float leaky1(float x) {
    const float SL = 1.0f / 5.5f;
    return x >= 0.f ? x : x * SL;
}
__device__ __forceinline__ float sigm1(float x) { return 1.f / (1.f + expf(-x)); }

// ---- packed fp32x2 FMA ----
#define FMA_X2(ACC, W, X) \
    asm("fma.rn.f32x2 %0, %1, %2, %0;" : "+l"(ACC) : "l"(W), "l"(X))

// ---- One RK4 stage: 576-thread field MLP; W2 comes from the persistent
//      per-thread register cache wreg[69] (this thread's full k-slice). ----
__device__ __forceinline__ void field_stage(int tid, float* sm, int stage,
        float2 dt, float2 tnext, bool write_in,
        const unsigned int* __restrict__ wreg,
        float rb1, float rb2a, float rb2b, float rb3) {
    float2* s_in  = (float2*)(sm + OFF_IN);
    float2* s_hid = (float2*)(sm + OFF_HID);
    float2* s_a2  = (float2*)(sm + OFF_A2);
    float2* s_y   = (float2*)(sm + OFF_Y);
    float2* s_ks  = (float2*)(sm + OFF_KS);
    float2* s_l1p = (float2*)(sm + OFF_PART);   // float2[275]
    float4* s_p4  = (float4*)(sm + OFF_PART);   // float4[414]
    float2* s_l3p = (float2*)(sm + OFF_PART);   // float2[300]

    int q = tid / 138, j = tid - q * 138;       // L2/L3 split
    bool actL2 = (q < 4);

    // ---- L1: 101 -> 275, k-split 2 ways (26 kp each; kp 51 is zero pad) ----
    int h = tid / 275, n = tid - h * 275;
    float2 l1acc = make_float2(0.f, 0.f);
    if (tid < 550) {
        const float2* wp = ((const float2*)(sm + OFF_W1P)) + n;
        const float4* x4 = (const float4*)(sm + OFF_IN);
        int kp0 = h * 26;
        float a0 = 0.f, a1 = 0.f, b0 = 0.f, b1 = 0.f;
#pragma unroll
        for (int u = 0; u < 26; u++) {
            float2 w = wp[(kp0 + u) * 275];
            float4 x = x4[kp0 + u];
            a0 = fmaf(w.x, x.x, a0); a1 = fmaf(w.x, x.y, a1);
            b0 = fmaf(w.y, x.z, b0); b1 = fmaf(w.y, x.w, b1);
        }
        l1acc = make_float2(a0 + b0, a1 + b1);
        if (h) s_l1p[n] = l1acc;
    }
    __syncthreads();
    if (tid < 275) {
        float2 p = s_l1p[tid];
        s_hid[tid] = make_float2(tanhf(l1acc.x + p.x + rb1),
                                 tanhf(l1acc.y + p.y + rb1));
    }
    __syncthreads();

    // ---- L2: 275 -> 275, W2 from registers, FMA2, k-split 4 ways ----
    float4 acc = make_float4(0.f, 0.f, 0.f, 0.f);
    if (actL2) {
        const ull* xu = (const ull*)(((const float2*)(sm + OFF_HID)) + q * 69);
        ull acA = 0ull, acA2 = 0ull, acB = 0ull, acB2 = 0ull;
#pragma unroll
        for (int i = 0; i < 69; i++) {
            float2 wf = __half22float2(*(const __half2*)&wreg[i]);
            ull wa, wb, xv = xu[i];
            asm("mov.b64 %0, {%1, %1};" : "=l"(wa) : "f"(wf.x));
            asm("mov.b64 %0, {%1, %1};" : "=l"(wb) : "f"(wf.y));
            if (i & 1) { FMA_X2(acA2, wa, xv); FMA_X2(acB2, wb, xv); }
            else       { FMA_X2(acA,  wa, xv); FMA_X2(acB,  wb, xv); }
        }
        ull sA, sB;
        asm("add.rn.f32x2 %0, %1, %2;" : "=l"(sA) : "l"(acA), "l"(acA2));
        asm("add.rn.f32x2 %0, %1, %2;" : "=l"(sB) : "l"(acB), "l"(acB2));
        float2 fA = *(float2*)&sA, fB = *(float2*)&sB;
        acc = make_float4(fA.x, fA.y, fB.x, fB.y);
        if (q) s_p4[(q - 1) * 138 + j] = acc;
    }
    __syncthreads();
    if (q == 0) {   // tid < 138
        float4 p1 = s_p4[j], p2 = s_p4[138 + j], p3 = s_p4[276 + j];
        float v0 = acc.x + p1.x + p2.x + p3.x + rb2a;
        float v1 = acc.y + p1.y + p2.y + p3.y + rb2a;
        float v2 = acc.z + p1.z + p2.z + p3.z + rb2b;
        float v3 = acc.w + p1.w + p2.w + p3.w + rb2b;
        s_a2[2 * j]     = make_float2(tanhf(v0), tanhf(v1));
        s_a2[2 * j + 1] = make_float2(tanhf(v2), tanhf(v3));
    }
    __syncthreads();

    // ---- L3: 275 -> 100, fp16 W3 in smem, k-split 4 ways (35 kp each) ----
    float2 l3acc = make_float2(0.f, 0.f);
    bool actL3 = actL2 && (j < 100);
    if (actL3) {
        const unsigned int* w3 = ((const unsigned int*)(sm + OFF_W3H)) + j;
        const float4* x4 = (const float4*)(sm + OFF_A2);
        int kp0 = q * 35;
        float a0 = 0.f, a1 = 0.f, b0 = 0.f, b1 = 0.f;
#pragma unroll
        for (int u = 0; u < 35; u++) {
            unsigned int wu = w3[(kp0 + u) * 100];
            float2 wf = __half22float2(*(const __half2*)&wu);
            float4 x = x4[kp0 + u];
            a0 = fmaf(wf.x, x.x, a0); a1 = fmaf(wf.x, x.y, a1);
            b0 = fmaf(wf.y, x.z, b0); b1 = fmaf(wf.y, x.w, b1);
        }
        l3acc = make_float2(a0 + b0, a1 + b1);
        if (q) s_l3p[(q - 1) * 100 + j] = l3acc;
    }
    __syncthreads();
    if (tid < 100) {
        float2 p1 = s_l3p[tid], p2 = s_l3p[100 + tid], p3 = s_l3p[200 + tid];
        float2 f = make_float2(tanhf(l3acc.x + p1.x + p2.x + p3.x + rb3),
                               tanhf(l3acc.y + p1.y + p2.y + p3.y + rb3));
        float2 y = s_y[tid];
        if (stage == 0) {
            s_ks[tid] = f;
            s_in[1 + tid] = make_float2(fmaf(0.5f * dt.x, f.x, y.x),
                                        fmaf(0.5f * dt.y, f.y, y.y));
        } else if (stage == 1) {
            float2 k = s_ks[tid];
            s_ks[tid] = make_float2(k.x + 2.f * f.x, k.y + 2.f * f.y);
            s_in[1 + tid] = make_float2(fmaf(0.5f * dt.x, f.x, y.x),
                                        fmaf(0.5f * dt.y, f.y, y.y));
        } else if (stage == 2) {
            float2 k = s_ks[tid];
            s_ks[tid] = make_float2(k.x + 2.f * f.x, k.y + 2.f * f.y);
            s_in[1 + tid] = make_float2(fmaf(dt.x, f.x, y.x),
                                        fmaf(dt.y, f.y, y.y));
        } else {
            float2 k = s_ks[tid];
            float2 yn = make_float2(y.x + dt.x * (k.x + f.x) / 6.f,
                                    y.y + dt.y * (k.y + f.y) / 6.f);
            s_y[tid] = yn;
            if (write_in) s_in[1 + tid] = yn;
        }
        if (tid == 0 && (stage < 3 || write_in)) s_in[0] = tnext;
    }
    __syncthreads();
}

// ---- RK4, NSUB=2 ----
__device__ __forceinline__ void integrate2(int tid, float* sm, float2 t0, float2 t1,
        const unsigned int* __restrict__ wreg,
        float rb1, float rb2a, float rb2b, float rb3) {
    float2* s_in = (float2*)(sm + OFF_IN);
    float2* s_y  = (float2*)(sm + OFF_Y);
    float2 dt = make_float2((t1.x - t0.x) * 0.5f, (t1.y - t0.y) * 0.5f);
    if (tid < HH) s_in[1 + tid] = s_y[tid];
    if (tid == 0) s_in[0] = t0;
    __syncthreads();
#pragma unroll 1
    for (int st = 0; st < 8; st++) {
        int stage = st & 3, sub = st >> 2;
        float2 tb = make_float2(t0.x + sub * dt.x, t0.y + sub * dt.y);
        float2 tnext = (stage <= 1)
            ? make_float2(tb.x + 0.5f * dt.x, tb.y + 0.5f * dt.y)
            : make_float2(tb.x + dt.x, tb.y + dt.y);
        field_stage(tid, sm, stage, dt, tnext, (st == 3), wreg,
                    rb1, rb2a, rb2b, rb3);
    }
}

// ---- load this thread's W2 slice into registers (69 half2) ----
#define W2REG_LOAD(wreg, tid)                                                 \
    {                                                                         \
        int q_ = (tid) / 138, j_ = (tid) - q_ * 138;                          \
        if (q_ < 4) {                                                         \
            const __half2* ph_ = g_W2H + (q_ * 69) * 138 + j_;                \
            _Pragma("unroll")                                                 \
            for (int i_ = 0; i_ < 69; i_++)                                   \
                wreg[i_] = *(const unsigned int*)(ph_ + i_ * 138);            \
        } else {                                                              \
            _Pragma("unroll")                                                 \
            for (int i_ = 0; i_ < 69; i_++) wreg[i_] = 0u;                    \
        }                                                                     \
    }

// ---- shared init common to encode/rollout ----
__device__ __forceinline__ void load_shared_weights(int tid, float* sm) {
    const float4* s1 = (const float4*)g_W1P;
    float4* d1 = (float4*)sm;
    for (int i = tid; i < 28600 / 4; i += NTHR) d1[i] = s1[i];
    const uint4* s2 = (const uint4*)g_W3H;
    uint4* d2 = (uint4*)(sm + OFF_W3H);
    for (int i = tid; i < 14000 / 4; i += NTHR) d2[i] = s2[i];
    if (tid == 0) {
        float2* s_in  = (float2*)(sm + OFF_IN);
        float2* s_hid = (float2*)(sm + OFF_HID);
        float2* s_a2  = (float2*)(sm + OFF_A2);
        s_in[101] = s_in[102] = s_in[103] = make_float2(0.f, 0.f);
        s_hid[275] = make_float2(0.f, 0.f);
        s_a2[276] = s_a2[277] = s_a2[278] = s_a2[279] = make_float2(0.f, 0.f);
    }
}

// ---- prep: build packed/transposed weight copies (identical to R13) ----
__global__ void prep_kernel(const float* __restrict__ fW1, const float* __restrict__ fW2,
                            const float* __restrict__ fW3, const float* __restrict__ Whh,
                            const float* __restrict__ oW1, const float* __restrict__ oW2) {
    for (int i = blockIdx.x * blockDim.x + threadIdx.x; i < 123813;
         i += gridDim.x * blockDim.x) {
        if (i < 28600) {
            int qq = i >> 1, r = i & 1;
            int kp = qq / 275, n = qq % 275;
            int k = 2 * kp + r;
            g_W1P[i] = (k < 101) ? fW1[n * 101 + k] : 0.f;
        } else if (i < 42600) {
            int idx = i - 28600;
            int kp = idx / 100, n = idx % 100;
            int k0 = 2 * kp, k1 = 2 * kp + 1;
            float v0 = (k0 < 275) ? fW3[n * 275 + k0] : 0.f;
            float v1 = (k1 < 275) ? fW3[n * 275 + k1] : 0.f;
            __half2 hv = __floats2half2_rn(v0, v1);
            g_W3H[idx] = *(unsigned int*)&hv;
        } else if (i < 80688) {
            int idx = i - 42600;
            int k = idx / 138, jj = idx % 138;
            int n0 = 2 * jj, n1 = 2 * jj + 1;
            float v0 = (k < 275) ? fW2[n0 * 275 + k] : 0.f;
            float v1 = (k < 275 && n1 < 275) ? fW2[n1 * 275 + k] : 0.f;
            g_W2H[idx] = __floats2half2_rn(v0, v1);
        } else if (i < 110688) {
            int jj = i - 80688, k = jj / 300, n = jj % 300;
            g_WhhT[jj] = Whh[n * 100 + k];
        } else if (i < 118188) {
            int jj = i - 110688, k = jj / 75, n = jj % 75;
            g_oW1T[jj] = oW1[n * 100 + k];
        } else {
            int jj = i - 118188, k = jj / 75, n = jj % 75;
            g_oW2T[jj] = oW2[n * 75 + k];
        }
    }
}

// ---- encode ----
__global__ void __launch_bounds__(NTHR, 1) encode_kernel(
        const float* __restrict__ past, const float* __restrict__ h0,
        const float* __restrict__ fb1, const float* __restrict__ fb2,
        const float* __restrict__ fb3,
        const float* __restrict__ Wih, const float* __restrict__ bih,
        const float* __restrict__ bhh) {
    extern __shared__ float sm[];
    int tid = threadIdx.x;
    int r0 = blockIdx.x * 2, r1 = r0 + 1;

    load_shared_weights(tid, sm);

    unsigned int wreg[69];
    W2REG_LOAD(wreg, tid)

    float rb1 = (tid < NF) ? __ldg(fb1 + tid) : 0.f;
    float rb2a = 0.f, rb2b = 0.f;
    if (tid < 138) {
        rb2a = __ldg(fb2 + 2 * tid);
        rb2b = (2 * tid + 1 < NF) ? __ldg(fb2 + 2 * tid + 1) : 0.f;
    }
    float rb3 = (tid < HH) ? __ldg(fb3 + tid) : 0.f;

    float2* s_y   = (float2*)(sm + OFF_Y);
    float2* s_u   = (float2*)(sm + OFF_HID);   // [200] aliased
    float2* s_inn = (float2*)(sm + OFF_A2);    // [100]
    float2* s_hn  = (float2*)(sm + OFF_PART);  // [100]
    if (tid < HH) s_y[tid] = make_float2(h0[r0 * HH + tid], h0[r1 * HH + tid]);
    __syncthreads();

    float2 tprev = make_float2(0.f, 0.f);
    for (int step = 0; step < TP; step++) {
        float2 tcur = make_float2(past[(r0 * TP + step) * 2], past[(r1 * TP + step) * 2]);
        float2 t0 = (step == 0) ? make_float2(tcur.x - 1.f, tcur.y - 1.f) : tprev;
        integrate2(tid, sm, t0, tcur, wreg, rb1, rb2a, rb2b, rb3);

        float2 x = make_float2(past[(r0 * TP + step) * 2 + 1],
                               past[(r1 * TP + step) * 2 + 1]);
        const float4* y4 = (const float4*)(sm + OFF_Y);
        if (tid < 300) {
            int jj = tid;
            float bh = __ldg(bhh + jj);
            float a0 = bh, a1 = bh, b0 = 0.f, b1 = 0.f;
#pragma unroll 10
            for (int k = 0; k < 100; k += 2) {
                float w0 = __ldcg(g_WhhT + k * 300 + jj);
                float w1 = __ldcg(g_WhhT + (k + 1) * 300 + jj);
                float4 y = y4[k >> 1];
                a0 = fmaf(w0, y.x, a0); a1 = fmaf(w0, y.y, a1);
                b0 = fmaf(w1, y.z, b0); b1 = fmaf(w1, y.w, b1);
            }
            a0 += b0; a1 += b1;
            float wi = __ldg(Wih + jj), bi = __ldg(bih + jj);
            float2 gi = make_float2(fmaf(wi, x.x, bi), fmaf(wi, x.y, bi));
            if (jj < 200) s_u[jj] = make_float2(gi.x + a0, gi.y + a1);
            else { s_inn[jj - 200] = gi; s_hn[jj - 200] = make_float2(a0, a1); }
        }
        __syncthreads();
        if (tid < HH) {
            float2 u1 = s_u[tid], u2 = s_u[HH + tid];
            float2 gin = s_inn[tid], ghn = s_hn[tid], hcur = s_y[tid];
            float rx = sigm1(u1.x), ry = sigm1(u1.y);
            float zx = sigm1(u2.x), zy = sigm1(u2.y);
            float nx = tanhf(gin.x + rx * ghn.x), ny = tanhf(gin.y + ry * ghn.y);
            s_y[tid] = make_float2((1.f - zx) * nx + zx * hcur.x,
                                   (1.f - zy) * ny + zy * hcur.y);
        }
        __syncthreads();
        tprev = tcur;
    }
    if (tid < HH) {
        g_hB[r0 * HH + tid] = s_y[tid].x;
        g_hB[r1 * HH + tid] = s_y[tid].y;
    }
}

// ---- decoder head ----
__global__ void gx_kernel(const float* __restrict__ gW1, const float* __restrict__ gb1,
                          const float* __restrict__ gW2, const float* __restrict__ gb2,
                          const float* __restrict__ gW3, const float* __restrict__ gb3) {
    int b = blockIdx.x, tid = threadIdx.x;
    __shared__ float sh[HH], s1[HGG], s2[HGG];
    for (int k = tid; k < HH; k += blockDim.x) sh[k] = g_hB[b * HH + k];
    __syncthreads();
    if (tid < HGG) {
        float a = __ldg(gb1 + tid);
        const float* w = gW1 + tid * HH;
        for (int k = 0; k < HH; k++) a = fmaf(__ldg(w + k), sh[k], a);
        s1[tid] = leaky1(a);
    }
    __syncthreads();
    if (tid < HGG) {
        float a = __ldg(gb2 + tid);
        const float* w = gW2 + tid * HGG;
        for (int k = 0; k < HGG; k++) a = fmaf(__ldg(w + k), s1[k], a);
        s2[tid] = leaky1(a);
    }
    __syncthreads();
    if (tid < 2) {
        float a = __ldg(gb3 + tid);
        const float* w = gW3 + tid * HGG;
        for (int k = 0; k < HGG; k++) a = fmaf(__ldg(w + k), s2[k], a);
        g_gx[b * 2 + tid] = a;
    }
}

__global__ void z0_kernel(const float* __restrict__ eps) {
    int b = blockIdx.x, h = threadIdx.x;
    float loc, scale;
    if (b < NB / 2) {
        loc   = g_gx[(2 * b) * 2 + 0];
        scale = g_gx[(2 * b + 1) * 2 + 0];
    } else {
        int i = 2 * (b - NB / 2);
        loc   = fabsf(g_gx[i * 2 + 1]);
        scale = fabsf(g_gx[(i + 1) * 2 + 1]);
    }
    g_z0[b * HH + h] = loc + scale * eps[h * NB + b];
}

// ---- rollout output MLP ----
__device__ __forceinline__ void out_mlp(int tid, int s, int r0, int r1, float* sm,
        float rob1, float rob2,
        const float* __restrict__ oW3, const float* __restrict__ ob3,
        float* __restrict__ out) {
    float2* s_o1 = (float2*)(sm + OFF_HID);
    float2* s_o2 = (float2*)(sm + OFF_A2);
    if (tid < HOO) {
        const float4* y4 = (const float4*)(sm + OFF_Y);
        float a0 = rob1, a1 = rob1, b0 = 0.f, b1 = 0.f;
#pragma unroll 10
        for (int k = 0; k < 100; k += 2) {
            float w0 = __ldcg(g_oW1T + k * 75 + tid);
            float w1 = __ldcg(g_oW1T + (k + 1) * 75 + tid);
            float4 y = y4[k >> 1];
            a0 = fmaf(w0, y.x, a0); a1 = fmaf(w0, y.y, a1);
            b0 = fmaf(w1, y.z, b0); b1 = fmaf(w1, y.w, b1);
        }
        s_o1[tid] = make_float2(leaky1(a0 + b0), leaky1(a1 + b1));
    }
    __syncthreads();
    if (tid < HOO) {
        const float4* h4 = (const float4*)(sm + OFF_HID);
        float a0 = rob2, a1 = rob2, b0 = 0.f, b1 = 0.f;
#pragma unroll 8
        for (int k = 0; k + 1 < HOO; k += 2) {
            float w0 = __ldcg(g_oW2T + k * 75 + tid);
            float w1 = __ldcg(g_oW2T + (k + 1) * 75 + tid);
            float4 h = h4[k >> 1];
            a0 = fmaf(w0, h.x, a0); a1 = fmaf(w0, h.y, a1);
            b0 = fmaf(w1, h.z, b0); b1 = fmaf(w1, h.w, b1);
        }
        {
            float w0 = __ldcg(g_oW2T + 74 * 75 + tid);
            float2 h = s_o1[74];
            a0 = fmaf(w0, h.x, a0); a1 = fmaf(w0, h.y, a1);
        }
        s_o2[tid] = make_float2(leaky1(a0 + b0), leaky1(a1 + b1));
    }
    __syncthreads();
    if (tid < 32) {
        float a0 = 0.f, a1 = 0.f;
        for (int k = tid; k < HOO; k += 32) {
            float wv = __ldg(oW3 + k);
            float2 h = s_o2[k];
            a0 = fmaf(wv, h.x, a0); a1 = fmaf(wv, h.y, a1);
        }
#pragma unroll
        for (int o = 16; o; o >>= 1) {
            a0 += __shfl_down_sync(0xffffffffu, a0, o);
            a1 += __shfl_down_sync(0xffffffffu, a1, o);
        }
        if (tid == 0) {
            float b = __ldg(ob3);
            out[r0 * TFUT + s] = a0 + b;
            out[r1 * TFUT + s] = a1 + b;
        }
    }
    __syncthreads();
}

__global__ void __launch_bounds__(NTHR, 1) rollout_kernel(
        const float* __restrict__ tf_,
        const float* __restrict__ fb1, const float* __restrict__ fb2,
        const float* __restrict__ fb3,
        const float* __restrict__ ob1, const float* __restrict__ ob2,
        const float* __restrict__ oW3, const float* __restrict__ ob3,
        float* __restrict__ out) {
    extern __shared__ float sm[];
    int tid = threadIdx.x;
    int r0 = blockIdx.x * 2, r1 = r0 + 1;

    load_shared_weights(tid, sm);

    unsigned int wreg[69];
    W2REG_LOAD(wreg, tid)

    float rb1 = (tid < NF) ? __ldg(fb1 + tid) : 0.f;
    float rb2a = 0.f, rb2b = 0.f;
    if (tid < 138) {
        rb2a = __ldg(fb2 + 2 * tid);
        rb2b = (2 * tid + 1 < NF) ? __ldg(fb2 + 2 * tid + 1) : 0.f;
    }
    float rb3 = (tid < HH) ? __ldg(fb3 + tid) : 0.f;
    float rob1 = (tid < HOO) ? __ldg(ob1 + tid) : 0.f;
    float rob2 = (tid < HOO) ? __ldg(ob2 + tid) : 0.f;

    float2* s_y = (float2*)(sm + OFF_Y);
    if (tid < HH) s_y[tid] = make_float2(g_z0[r0 * HH + tid], g_z0[r1 * HH + tid]);
    __syncthreads();

    out_mlp(tid, 0, r0, r1, sm, rob1, rob2, oW3, ob3, out);

    float2 tprev = make_float2(tf_[r0 * TFUT], tf_[r1 * TFUT]);
    for (int s = 1; s < TFUT; s++) {
        float2 tcur = make_float2(tf_[r0 * TFUT + s], tf_[r1 * TFUT + s]);
        integrate2(tid, sm, tprev, tcur, wreg, rb1, rb2a, rb2b, rb3);
        out_mlp(tid, s, r0, r1, sm, rob1, rob2, oW3, ob3, out);
        tprev = tcur;
    }
}

extern "C" void kernel_launch(void* const* d_in, const int* in_sizes, int n_in,
                              void* d_out, int out_size) {
    const float* past = (const float*)d_in[0];
    const float* h0   = (const float*)d_in[1];
    const float* t_fu = (const float*)d_in[2];
    const float* eps  = (const float*)d_in[3];
    const float* fW1  = (const float*)d_in[4];
    const float* fb1  = (const float*)d_in[5];
    const float* fW2  = (const float*)d_in[6];
    const float* fb2  = (const float*)d_in[7];
    const float* fW3  = (const float*)d_in[8];
    const float* fb3  = (const float*)d_in[9];
    const float* Wih  = (const float*)d_in[10];
    const float* Whh  = (const float*)d_in[11];
    const float* bih  = (const float*)d_in[12];
    const float* bhh  = (const float*)d_in[13];
    const float* gW1  = (const float*)d_in[14];
    const float* gb1  = (const float*)d_in[15];
    const float* gW2  = (const float*)d_in[16];
    const float* gb2  = (const float*)d_in[17];
    const float* gW3  = (const float*)d_in[18];
    const float* gb3  = (const float*)d_in[19];
    const float* oW1  = (const float*)d_in[20];
    const float* ob1  = (const float*)d_in[21];
    const float* oW2  = (const float*)d_in[22];
    const float* ob2  = (const float*)d_in[23];
    const float* oW3  = (const float*)d_in[24];
    const float* ob3  = (const float*)d_in[25];
    float* out = (float*)d_out;

    static bool attr_done = false;
    if (!attr_done) {
        cudaFuncSetAttribute(encode_kernel,
                             cudaFuncAttributeMaxDynamicSharedMemorySize, SMEM_BYTES);
        cudaFuncSetAttribute(rollout_kernel,
                             cudaFuncAttributeMaxDynamicSharedMemorySize, SMEM_BYTES);
        attr_done = true;
    }

    prep_kernel<<<192, 256>>>(fW1, fW2, fW3, Whh, oW1, oW2);
    encode_kernel<<<NCTA, NTHR, SMEM_BYTES>>>(past, h0, fb1, fb2, fb3, Wih, bih, bhh);
    gx_kernel<<<NB, 96>>>(gW1, gb1, gW2, gb2, gW3, gb3);
    z0_kernel<<<NB, HH>>>(eps);
    rollout_kernel<<<NCTA, NTHR, SMEM_BYTES>>>(t_fu, fb1, fb2, fb3,
                                               ob1, ob2, oW3, ob3, out);
}